// round 5
// baseline (speedup 1.0000x reference)
#include <cuda_runtime.h>

// S2Conv fused persistent kernel, v2 (2 CTAs/SM).
// N=64, C=128, T=2048, S=9. 256 blocks x 512 threads.
// Block = 32 output channels x (4 slabs of 512 t). Phase 1: conv -> out,
// stats in regs. Grid barrier. Phase 2: normalize out in-place (L2-hot).

#define Nn 64
#define Cc 128
#define Tt 2048
#define Ss 9
#define CG 32          // output channels per block
#define ROWS 40        // CG + 8 halo
#define TBt 512        // time tile
#define NBLK 256
#define NTHR 512

__device__ float g_sum[Cc];
__device__ float g_sumsq[Cc];
__device__ unsigned g_arrive;

__global__ void init_kernel() {
    int i = threadIdx.x;
    if (i < Cc) { g_sum[i] = 0.0f; g_sumsq[i] = 0.0f; }
    if (i == 0) g_arrive = 0u;
}

extern __shared__ float tile_mem[];   // ROWS x TBt floats = 80 KB

__global__ __launch_bounds__(NTHR, 2) void fused_kernel(
    const float* __restrict__ x,
    const float* __restrict__ w,
    const float* __restrict__ gamma,
    const float* __restrict__ beta,
    float* __restrict__ out)
{
    float (*tile)[TBt] = (float (*)[TBt])tile_mem;
    __shared__ float s_w[CG][12];          // padded
    __shared__ float s_scale[CG], s_bias[CG];

    const int bid  = blockIdx.x;
    const int grp  = bid >> 6;             // 0..3 channel group
    const int sb   = bid & 63;             // 0..63 slab block
    const int cg0  = grp * CG;
    const int tid  = threadIdx.x;
    const int wid  = tid >> 5;
    const int lane = tid & 31;
    const int g    = wid & 7;              // channel quad within group
    const int q    = wid >> 3;             // t half (0/1)
    const int lcb  = g * 4;

    if (tid < CG * Ss) {
        int cl = tid / Ss, s = tid % Ss;
        s_w[cl][s] = w[(cg0 + cl) * Ss + s];
    }

    float lsum[4] = {0.f, 0.f, 0.f, 0.f};
    float lsq[4]  = {0.f, 0.f, 0.f, 0.f};

    for (int sl = 0; sl < 4; sl++) {
        const int slab = sb * 4 + sl;      // 0..255
        const int n    = slab >> 2;
        const int t0   = (slab & 3) * TBt;

        __syncthreads();                   // tile reuse guard (covers s_w on sl=0)

        // ---- Loader: tile[r][j] = xs[n, cg0-4+r, t0+j], pre-shifted, zero-padded.
        const float* xn = x + (size_t)n * Cc * Tt;
        for (int r = wid; r < ROWS; r += 16) {
            const int cc = cg0 - 4 + r;
            const bool rowok = (cc >= 0) && (cc < Cc);
            const int off = rowok ? (4 - (cc % 9)) : 0;
            const float* xr = xn + (size_t)(rowok ? cc : 0) * Tt;
            #pragma unroll
            for (int u = 0; u < TBt / 128; u++) {
                const int j  = u * 128 + lane * 4;
                const int ts = t0 + j + off;
                float4 v = make_float4(0.f, 0.f, 0.f, 0.f);
                if (rowok) {
                    if ((unsigned)(ts + 0) < (unsigned)Tt) v.x = xr[ts + 0];
                    if ((unsigned)(ts + 1) < (unsigned)Tt) v.y = xr[ts + 1];
                    if ((unsigned)(ts + 2) < (unsigned)Tt) v.z = xr[ts + 2];
                    if ((unsigned)(ts + 3) < (unsigned)Tt) v.w = xr[ts + 3];
                }
                *reinterpret_cast<float4*>(&tile[r][j]) = v;
            }
        }
        __syncthreads();

        // ---- Compute: warp (g,q) -> 4 channels x 256 t; lane -> 4 t per iter.
        // Streamed taps: row r feeds acc[cl] for cl in [r-8, r] cap [0,4).
        float* outb = out + ((size_t)n * Cc + cg0 + lcb) * Tt + t0;
        #pragma unroll
        for (int it = 0; it < 2; it++) {
            const int j = q * 256 + it * 128 + lane * 4;
            float4 acc[4];
            #pragma unroll
            for (int cl = 0; cl < 4; cl++) acc[cl] = make_float4(0.f, 0.f, 0.f, 0.f);
            #pragma unroll
            for (int r = 0; r < 12; r++) {
                const float4 tp = *reinterpret_cast<const float4*>(&tile[lcb + r][j]);
                const int cl_lo = (r > 8) ? (r - 8) : 0;
                const int cl_hi = (r < 3) ? r : 3;
                #pragma unroll
                for (int cl = 0; cl < 4; cl++) {
                    if (cl >= cl_lo && cl <= cl_hi) {
                        const float wv = s_w[lcb + cl][r - cl];
                        acc[cl].x = fmaf(wv, tp.x, acc[cl].x);
                        acc[cl].y = fmaf(wv, tp.y, acc[cl].y);
                        acc[cl].z = fmaf(wv, tp.z, acc[cl].z);
                        acc[cl].w = fmaf(wv, tp.w, acc[cl].w);
                    }
                }
            }
            #pragma unroll
            for (int cl = 0; cl < 4; cl++) {
                const float4 a = acc[cl];
                *reinterpret_cast<float4*>(outb + (size_t)cl * Tt + j) = a;
                lsum[cl] += (a.x + a.y) + (a.z + a.w);
                lsq[cl]   = fmaf(a.x, a.x, fmaf(a.y, a.y,
                            fmaf(a.z, a.z, fmaf(a.w, a.w, lsq[cl]))));
            }
        }
    }

    // ---- One reduction for the whole kernel.
    #pragma unroll
    for (int cl = 0; cl < 4; cl++) {
        #pragma unroll
        for (int o = 16; o > 0; o >>= 1) {
            lsum[cl] += __shfl_down_sync(0xffffffffu, lsum[cl], o);
            lsq[cl]  += __shfl_down_sync(0xffffffffu, lsq[cl],  o);
        }
    }
    if (lane == 0) {
        #pragma unroll
        for (int cl = 0; cl < 4; cl++) {
            atomicAdd(&g_sum[cg0 + lcb + cl],   lsum[cl]);
            atomicAdd(&g_sumsq[cg0 + lcb + cl], lsq[cl]);
        }
    }
    __syncthreads();

    // ---- Grid barrier (256 blocks, all resident at 2 CTAs/SM).
    if (tid == 0) {
        __threadfence();
        atomicAdd(&g_arrive, 1u);
        while (*(volatile unsigned*)&g_arrive < NBLK) { }
    }
    __syncthreads();
    __threadfence();

    // ---- Finalize per-channel scale/bias.
    if (tid < CG) {
        const int c = cg0 + tid;
        const float s1 = __ldcg(&g_sum[c]);
        const float s2 = __ldcg(&g_sumsq[c]);
        const float inv = 1.0f / ((float)Nn * (float)Tt);
        const float mean = s1 * inv;
        const float var  = s2 * inv - mean * mean;
        const float rstd = rsqrtf(var + 1e-5f);
        const float sc   = gamma[c] * rstd;
        s_scale[tid] = sc;
        s_bias[tid]  = beta[c] - mean * sc;
    }
    __syncthreads();

    // ---- Phase 2: normalize + relu the region this block wrote (L2-hot).
    for (int sl = 0; sl < 4; sl++) {
        const int slab = sb * 4 + sl;
        const int n    = slab >> 2;
        const int t0   = (slab & 3) * TBt;
        float* ob = out + ((size_t)n * Cc + cg0) * Tt + t0;
        #pragma unroll
        for (int k = 0; k < (CG * TBt / 4) / NTHR; k++) {
            const int idx = tid + k * NTHR;
            const int row = idx >> 7;            // 128 float4 per row
            const int col = (idx & 127) * 4;
            float4 v = *reinterpret_cast<float4*>(ob + (size_t)row * Tt + col);
            const float sc = s_scale[row];
            const float b  = s_bias[row];
            v.x = fmaxf(fmaf(v.x, sc, b), 0.0f);
            v.y = fmaxf(fmaf(v.y, sc, b), 0.0f);
            v.z = fmaxf(fmaf(v.z, sc, b), 0.0f);
            v.w = fmaxf(fmaf(v.w, sc, b), 0.0f);
            *reinterpret_cast<float4*>(ob + (size_t)row * Tt + col) = v;
        }
    }
}

extern "C" void kernel_launch(void* const* d_in, const int* in_sizes, int n_in,
                              void* d_out, int out_size)
{
    const float* x     = (const float*)d_in[0];
    const float* w     = (const float*)d_in[1];
    const float* gamma = (const float*)d_in[2];
    const float* beta  = (const float*)d_in[3];
    float* out = (float*)d_out;

    const int smem = ROWS * TBt * sizeof(float);   // 80 KB dynamic
    static bool attr_set = false;
    if (!attr_set) {
        cudaFuncSetAttribute(fused_kernel,
                             cudaFuncAttributeMaxDynamicSharedMemorySize, smem);
        attr_set = true;
    }

    init_kernel<<<1, 128>>>();
    fused_kernel<<<NBLK, NTHR, smem>>>(x, w, gamma, beta, out);
}

// round 6
// speedup vs baseline: 1.0287x; 1.0287x over previous
#include <cuda_runtime.h>

// S2Conv fused persistent kernel, v2 (2 CTAs/SM).
// N=64, C=128, T=2048, S=9. 256 blocks x 512 threads.
// Block = 32 output channels x (4 slabs of 512 t). Phase 1: conv -> out,
// stats in regs. Grid barrier. Phase 2: normalize out in-place (L2-hot).

#define Nn 64
#define Cc 128
#define Tt 2048
#define Ss 9
#define CG 32          // output channels per block
#define ROWS 40        // CG + 8 halo
#define TBt 512        // time tile
#define NBLK 256
#define NTHR 512

__device__ float g_sum[Cc];
__device__ float g_sumsq[Cc];
__device__ unsigned g_arrive;

__global__ void init_kernel() {
    int i = threadIdx.x;
    if (i < Cc) { g_sum[i] = 0.0f; g_sumsq[i] = 0.0f; }
    if (i == 0) g_arrive = 0u;
}

extern __shared__ float tile_mem[];   // ROWS x TBt floats = 80 KB

__global__ __launch_bounds__(NTHR, 2) void fused_kernel(
    const float* __restrict__ x,
    const float* __restrict__ w,
    const float* __restrict__ gamma,
    const float* __restrict__ beta,
    float* __restrict__ out)
{
    float (*tile)[TBt] = (float (*)[TBt])tile_mem;
    __shared__ float s_w[CG][12];          // padded
    __shared__ float s_scale[CG], s_bias[CG];

    const int bid  = blockIdx.x;
    const int grp  = bid >> 6;             // 0..3 channel group
    const int sb   = bid & 63;             // 0..63 slab block
    const int cg0  = grp * CG;
    const int tid  = threadIdx.x;
    const int wid  = tid >> 5;
    const int lane = tid & 31;
    const int g    = wid & 7;              // channel quad within group
    const int q    = wid >> 3;             // t half (0/1)
    const int lcb  = g * 4;

    if (tid < CG * Ss) {
        int cl = tid / Ss, s = tid % Ss;
        s_w[cl][s] = w[(cg0 + cl) * Ss + s];
    }

    float lsum[4] = {0.f, 0.f, 0.f, 0.f};
    float lsq[4]  = {0.f, 0.f, 0.f, 0.f};

    for (int sl = 0; sl < 4; sl++) {
        const int slab = sb * 4 + sl;      // 0..255
        const int n    = slab >> 2;
        const int t0   = (slab & 3) * TBt;

        __syncthreads();                   // tile reuse guard (covers s_w on sl=0)

        // ---- Loader: tile[r][j] = xs[n, cg0-4+r, t0+j], pre-shifted, zero-padded.
        const float* xn = x + (size_t)n * Cc * Tt;
        for (int r = wid; r < ROWS; r += 16) {
            const int cc = cg0 - 4 + r;
            const bool rowok = (cc >= 0) && (cc < Cc);
            const int off = rowok ? (4 - (cc % 9)) : 0;
            const float* xr = xn + (size_t)(rowok ? cc : 0) * Tt;
            #pragma unroll
            for (int u = 0; u < TBt / 128; u++) {
                const int j  = u * 128 + lane * 4;
                const int ts = t0 + j + off;
                float4 v = make_float4(0.f, 0.f, 0.f, 0.f);
                if (rowok) {
                    if ((unsigned)(ts + 0) < (unsigned)Tt) v.x = xr[ts + 0];
                    if ((unsigned)(ts + 1) < (unsigned)Tt) v.y = xr[ts + 1];
                    if ((unsigned)(ts + 2) < (unsigned)Tt) v.z = xr[ts + 2];
                    if ((unsigned)(ts + 3) < (unsigned)Tt) v.w = xr[ts + 3];
                }
                *reinterpret_cast<float4*>(&tile[r][j]) = v;
            }
        }
        __syncthreads();

        // ---- Compute: warp (g,q) -> 4 channels x 256 t; lane -> 4 t per iter.
        // Streamed taps: row r feeds acc[cl] for cl in [r-8, r] cap [0,4).
        float* outb = out + ((size_t)n * Cc + cg0 + lcb) * Tt + t0;
        #pragma unroll
        for (int it = 0; it < 2; it++) {
            const int j = q * 256 + it * 128 + lane * 4;
            float4 acc[4];
            #pragma unroll
            for (int cl = 0; cl < 4; cl++) acc[cl] = make_float4(0.f, 0.f, 0.f, 0.f);
            #pragma unroll
            for (int r = 0; r < 12; r++) {
                const float4 tp = *reinterpret_cast<const float4*>(&tile[lcb + r][j]);
                const int cl_lo = (r > 8) ? (r - 8) : 0;
                const int cl_hi = (r < 3) ? r : 3;
                #pragma unroll
                for (int cl = 0; cl < 4; cl++) {
                    if (cl >= cl_lo && cl <= cl_hi) {
                        const float wv = s_w[lcb + cl][r - cl];
                        acc[cl].x = fmaf(wv, tp.x, acc[cl].x);
                        acc[cl].y = fmaf(wv, tp.y, acc[cl].y);
                        acc[cl].z = fmaf(wv, tp.z, acc[cl].z);
                        acc[cl].w = fmaf(wv, tp.w, acc[cl].w);
                    }
                }
            }
            #pragma unroll
            for (int cl = 0; cl < 4; cl++) {
                const float4 a = acc[cl];
                *reinterpret_cast<float4*>(outb + (size_t)cl * Tt + j) = a;
                lsum[cl] += (a.x + a.y) + (a.z + a.w);
                lsq[cl]   = fmaf(a.x, a.x, fmaf(a.y, a.y,
                            fmaf(a.z, a.z, fmaf(a.w, a.w, lsq[cl]))));
            }
        }
    }

    // ---- One reduction for the whole kernel.
    #pragma unroll
    for (int cl = 0; cl < 4; cl++) {
        #pragma unroll
        for (int o = 16; o > 0; o >>= 1) {
            lsum[cl] += __shfl_down_sync(0xffffffffu, lsum[cl], o);
            lsq[cl]  += __shfl_down_sync(0xffffffffu, lsq[cl],  o);
        }
    }
    if (lane == 0) {
        #pragma unroll
        for (int cl = 0; cl < 4; cl++) {
            atomicAdd(&g_sum[cg0 + lcb + cl],   lsum[cl]);
            atomicAdd(&g_sumsq[cg0 + lcb + cl], lsq[cl]);
        }
    }
    __syncthreads();

    // ---- Grid barrier (256 blocks, all resident at 2 CTAs/SM).
    if (tid == 0) {
        __threadfence();
        atomicAdd(&g_arrive, 1u);
        while (*(volatile unsigned*)&g_arrive < NBLK) { }
    }
    __syncthreads();
    __threadfence();

    // ---- Finalize per-channel scale/bias.
    if (tid < CG) {
        const int c = cg0 + tid;
        const float s1 = __ldcg(&g_sum[c]);
        const float s2 = __ldcg(&g_sumsq[c]);
        const float inv = 1.0f / ((float)Nn * (float)Tt);
        const float mean = s1 * inv;
        const float var  = s2 * inv - mean * mean;
        const float rstd = rsqrtf(var + 1e-5f);
        const float sc   = gamma[c] * rstd;
        s_scale[tid] = sc;
        s_bias[tid]  = beta[c] - mean * sc;
    }
    __syncthreads();

    // ---- Phase 2: normalize + relu the region this block wrote (L2-hot).
    for (int sl = 0; sl < 4; sl++) {
        const int slab = sb * 4 + sl;
        const int n    = slab >> 2;
        const int t0   = (slab & 3) * TBt;
        float* ob = out + ((size_t)n * Cc + cg0) * Tt + t0;
        #pragma unroll
        for (int k = 0; k < (CG * TBt / 4) / NTHR; k++) {
            const int idx = tid + k * NTHR;
            const int row = idx >> 7;            // 128 float4 per row
            const int col = (idx & 127) * 4;
            float4 v = *reinterpret_cast<float4*>(ob + (size_t)row * Tt + col);
            const float sc = s_scale[row];
            const float b  = s_bias[row];
            v.x = fmaxf(fmaf(v.x, sc, b), 0.0f);
            v.y = fmaxf(fmaf(v.y, sc, b), 0.0f);
            v.z = fmaxf(fmaf(v.z, sc, b), 0.0f);
            v.w = fmaxf(fmaf(v.w, sc, b), 0.0f);
            *reinterpret_cast<float4*>(ob + (size_t)row * Tt + col) = v;
        }
    }
}

extern "C" void kernel_launch(void* const* d_in, const int* in_sizes, int n_in,
                              void* d_out, int out_size)
{
    const float* x     = (const float*)d_in[0];
    const float* w     = (const float*)d_in[1];
    const float* gamma = (const float*)d_in[2];
    const float* beta  = (const float*)d_in[3];
    float* out = (float*)d_out;

    const int smem = ROWS * TBt * sizeof(float);   // 80 KB dynamic
    static bool attr_set = false;
    if (!attr_set) {
        cudaFuncSetAttribute(fused_kernel,
                             cudaFuncAttributeMaxDynamicSharedMemorySize, smem);
        attr_set = true;
    }

    init_kernel<<<1, 128>>>();
    fused_kernel<<<NBLK, NTHR, smem>>>(x, w, gamma, beta, out);
}

// round 7
// speedup vs baseline: 1.0525x; 1.0232x over previous
#include <cuda_runtime.h>

// S2Conv fused persistent kernel, v3: warp-specialized producer/consumer
// pipeline with double-buffered smem tiles.
// N=64, C=128, T=2048, S=9. 128 blocks x 1024 threads (1 CTA/SM).
// Block = 32 output channels x 8 slabs (each 1 n x 512 t).
// Warps 0-15 consume (conv + stats), warps 16-31 produce (tile loads).

#define Nn 64
#define Cc 128
#define Tt 2048
#define Ss 9
#define CG 32          // output channels per block
#define ROWS 40        // CG + 8 halo
#define TBt 512        // time tile
#define NBLK 128
#define NTHR 1024
#define NSLAB 8

__device__ float g_sum[Cc];
__device__ float g_sumsq[Cc];
__device__ unsigned g_arrive;

__global__ void init_kernel() {
    int i = threadIdx.x;
    if (i < Cc) { g_sum[i] = 0.0f; g_sumsq[i] = 0.0f; }
    if (i == 0) g_arrive = 0u;
}

// Named barriers: full[b] = 1+b, empty[b] = 3+b. Count = all 1024 threads.
#define BAR_SYNC(id)   asm volatile("bar.sync %0, 1024;"   :: "r"(id) : "memory")
#define BAR_ARRIVE(id) asm volatile("bar.arrive %0, 1024;" :: "r"(id) : "memory")

extern __shared__ float tile_mem[];   // 2 x ROWS x TBt = 160 KB

__global__ __launch_bounds__(NTHR, 1) void fused_kernel(
    const float* __restrict__ x,
    const float* __restrict__ w,
    const float* __restrict__ gamma,
    const float* __restrict__ beta,
    float* __restrict__ out)
{
    __shared__ float s_w[CG][12];          // padded
    __shared__ float s_scale[CG], s_bias[CG];

    const int bid  = blockIdx.x;
    const int grp  = bid >> 5;             // 0..3 channel group
    const int sb   = bid & 31;             // 0..31 slab block (covers n = 2sb, 2sb+1)
    const int cg0  = grp * CG;
    const int tid  = threadIdx.x;
    const int wid  = tid >> 5;
    const int lane = tid & 31;

    if (tid < CG * Ss) {
        int cl = tid / Ss, s = tid % Ss;
        s_w[cl][s] = w[(cg0 + cl) * Ss + s];
    }

    float lsum[4] = {0.f, 0.f, 0.f, 0.f};
    float lsq[4]  = {0.f, 0.f, 0.f, 0.f};

    if (wid >= 16) {
        // ================= PRODUCER: warps 16..31 =================
        const int ptid = tid - 512;
        for (int sl = 0; sl < NSLAB; sl++) {
            const int slab = sb * NSLAB + sl;
            const int n    = slab >> 2;
            const int t0   = (slab & 3) * TBt;
            const int b    = sl & 1;
            if (sl >= 2) BAR_SYNC(3 + b);
            float* buf = tile_mem + b * (ROWS * TBt);
            const float* xn = x + (size_t)n * Cc * Tt;
            // tile[r][j] = xs[n, cg0-4+r, t0+j]; xs[cc,t] = x[cc, t+4-cc%9], zero-pad.
            #pragma unroll
            for (int k = 0; k < (ROWS * TBt / 4) / 512; k++) {   // 10 chunks
                const int ci = ptid + k * 512;
                const int r  = ci >> 7;               // 128 float4 per row
                const int j  = (ci & 127) * 4;
                const int cc = cg0 - 4 + r;
                const bool rowok = (cc >= 0) && (cc < Cc);
                const int off = rowok ? (4 - (cc % 9)) : 0;
                const float* xr = xn + (size_t)(rowok ? cc : 0) * Tt;
                const int ts = t0 + j + off;
                float4 v = make_float4(0.f, 0.f, 0.f, 0.f);
                if (rowok) {
                    if ((unsigned)(ts + 0) < (unsigned)Tt) v.x = __ldcs(&xr[ts + 0]);
                    if ((unsigned)(ts + 1) < (unsigned)Tt) v.y = __ldcs(&xr[ts + 1]);
                    if ((unsigned)(ts + 2) < (unsigned)Tt) v.z = __ldcs(&xr[ts + 2]);
                    if ((unsigned)(ts + 3) < (unsigned)Tt) v.w = __ldcs(&xr[ts + 3]);
                }
                *reinterpret_cast<float4*>(&buf[r * TBt + j]) = v;
            }
            __threadfence_block();
            BAR_ARRIVE(1 + b);
        }
    } else {
        // ================= CONSUMER: warps 0..15 =================
        const int g   = wid & 7;           // channel quad
        const int q   = wid >> 3;          // t half (0/1)
        const int lcb = g * 4;
        for (int sl = 0; sl < NSLAB; sl++) {
            const int slab = sb * NSLAB + sl;
            const int n    = slab >> 2;
            const int t0   = (slab & 3) * TBt;
            const int b    = sl & 1;
            BAR_SYNC(1 + b);
            const float* buf = tile_mem + b * (ROWS * TBt);
            float* outb = out + ((size_t)n * Cc + cg0 + lcb) * Tt + t0;
            #pragma unroll
            for (int it = 0; it < 2; it++) {
                const int j = q * 256 + it * 128 + lane * 4;
                float4 acc[4];
                #pragma unroll
                for (int cl = 0; cl < 4; cl++) acc[cl] = make_float4(0.f, 0.f, 0.f, 0.f);
                #pragma unroll
                for (int r = 0; r < 12; r++) {
                    const float4 tp = *reinterpret_cast<const float4*>(
                        &buf[(lcb + r) * TBt + j]);
                    const int cl_lo = (r > 8) ? (r - 8) : 0;
                    const int cl_hi = (r < 3) ? r : 3;
                    #pragma unroll
                    for (int cl = 0; cl < 4; cl++) {
                        if (cl >= cl_lo && cl <= cl_hi) {
                            const float wv = s_w[lcb + cl][r - cl];
                            acc[cl].x = fmaf(wv, tp.x, acc[cl].x);
                            acc[cl].y = fmaf(wv, tp.y, acc[cl].y);
                            acc[cl].z = fmaf(wv, tp.z, acc[cl].z);
                            acc[cl].w = fmaf(wv, tp.w, acc[cl].w);
                        }
                    }
                }
                #pragma unroll
                for (int cl = 0; cl < 4; cl++) {
                    const float4 a = acc[cl];
                    *reinterpret_cast<float4*>(outb + (size_t)cl * Tt + j) = a;
                    lsum[cl] += (a.x + a.y) + (a.z + a.w);
                    lsq[cl]   = fmaf(a.x, a.x, fmaf(a.y, a.y,
                                fmaf(a.z, a.z, fmaf(a.w, a.w, lsq[cl]))));
                }
            }
            BAR_ARRIVE(3 + b);
        }
        // One reduction for the whole kernel.
        #pragma unroll
        for (int cl = 0; cl < 4; cl++) {
            #pragma unroll
            for (int o = 16; o > 0; o >>= 1) {
                lsum[cl] += __shfl_down_sync(0xffffffffu, lsum[cl], o);
                lsq[cl]  += __shfl_down_sync(0xffffffffu, lsq[cl],  o);
            }
        }
        if (lane == 0) {
            #pragma unroll
            for (int cl = 0; cl < 4; cl++) {
                atomicAdd(&g_sum[cg0 + lcb + cl],   lsum[cl]);
                atomicAdd(&g_sumsq[cg0 + lcb + cl], lsq[cl]);
            }
        }
    }

    __syncthreads();

    // ---- Grid barrier (128 blocks, all resident at 1 CTA/SM).
    if (tid == 0) {
        __threadfence();
        atomicAdd(&g_arrive, 1u);
        while (*(volatile unsigned*)&g_arrive < NBLK) { }
    }
    __syncthreads();
    __threadfence();

    // ---- Finalize per-channel scale/bias.
    if (tid < CG) {
        const int c = cg0 + tid;
        const float s1 = __ldcg(&g_sum[c]);
        const float s2 = __ldcg(&g_sumsq[c]);
        const float inv = 1.0f / ((float)Nn * (float)Tt);
        const float mean = s1 * inv;
        const float var  = s2 * inv - mean * mean;
        const float rstd = rsqrtf(var + 1e-5f);
        const float sc   = gamma[c] * rstd;
        s_scale[tid] = sc;
        s_bias[tid]  = beta[c] - mean * sc;
    }
    __syncthreads();

    // ---- Phase 2: normalize + relu the region this block wrote (L2-hot).
    // Region: n in {2sb, 2sb+1}, channels cg0..cg0+31, all t.
    float* ob = out + ((size_t)(2 * sb) * Cc + cg0) * Tt;
    #pragma unroll 4
    for (int k = 0; k < (2 * CG * Tt / 4) / NTHR; k++) {   // 32 iters
        const int idx = tid + k * NTHR;
        const int row = idx >> 9;            // 512 float4 per (n,ch) row
        const int nn  = row >> 5;
        const int ch  = row & 31;
        const int col = (idx & 511) * 4;
        float* p = ob + ((size_t)nn * Cc + ch) * Tt + col;
        float4 v = *reinterpret_cast<float4*>(p);
        const float sc = s_scale[ch];
        const float bs = s_bias[ch];
        v.x = fmaxf(fmaf(v.x, sc, bs), 0.0f);
        v.y = fmaxf(fmaf(v.y, sc, bs), 0.0f);
        v.z = fmaxf(fmaf(v.z, sc, bs), 0.0f);
        v.w = fmaxf(fmaf(v.w, sc, bs), 0.0f);
        *reinterpret_cast<float4*>(p) = v;
    }
}

extern "C" void kernel_launch(void* const* d_in, const int* in_sizes, int n_in,
                              void* d_out, int out_size)
{
    const float* x     = (const float*)d_in[0];
    const float* w     = (const float*)d_in[1];
    const float* gamma = (const float*)d_in[2];
    const float* beta  = (const float*)d_in[3];
    float* out = (float*)d_out;

    const int smem = 2 * ROWS * TBt * sizeof(float);   // 160 KB dynamic
    static bool attr_set = false;
    if (!attr_set) {
        cudaFuncSetAttribute(fused_kernel,
                             cudaFuncAttributeMaxDynamicSharedMemorySize, smem);
        attr_set = true;
    }

    init_kernel<<<1, 128>>>();
    fused_kernel<<<NBLK, NTHR, smem>>>(x, w, gamma, beta, out);
}